// round 11
// baseline (speedup 1.0000x reference)
#include <cuda_runtime.h>
#include <cuda_bf16.h>
#include <stdint.h>
#include <stddef.h>

// Problem: B=128, S=512, I=128, Hd=512.
//   gi = x @ Wc^T + bc,  Wc = w_ih @ w_emb (1536 x 128), bc = b_ih + w_ih @ b_emb
//   r = sigmoid(gi_r + b_hr); z = sigmoid(gi_z + b_hz)
//   n = tanh(gi_n + r * b_hn); h = (1-z)*n
//   out = [ H = h[:, :511, :] | h_last = h[:, 511, :] ]
//
// GEMM M=65536, N=1536, K=128 done as bf16x3 (hi*hi + hi*lo + lo*hi), fp32 acc,
// via mma.sync.m16n8k16 (base-PTX tensor path; tcgen05 is rejected by the
// harness's compute_103 ptxas pass).

static constexpr int NUM_MT  = 512;   // 65536 / 128 row tiles
static constexpr int NUM_HDT = 16;    // 512 / 32 hd tiles
static constexpr long H_OFF  = 128L * 511L * 512L;

// ---------------- device scratch ----------------
// X per m-tile: 128 rows x 128 k bf16, 256B/row, XOR-swizzled 16B chunks.
__device__ __nv_bfloat16 g_Xhi[512][16384];
__device__ __nv_bfloat16 g_Xlo[512][16384];
// W per hd-tile: 2 segs (hi, lo), 96 rows x 128 k each, same layout.
// Row order within tile: n = sub*24 + gate*8 + within   (sub = hd_t/8, within = hd_t%8)
__device__ __nv_bfloat16 g_W[16][2][12288];
// biases: [0..512)=bc_r+b_hr  [512..1024)=bc_z+b_hz  [1024..1536)=bc_n  [1536..2048)=b_hn
__device__ float g_bias[2048];

// XOR swizzle: byte offset of element (row, k) inside a tile (128 k per row).
__device__ __forceinline__ int sw_off(int row, int k) {
    const int chunk = k >> 3;
    const int phys  = (chunk & 8) | ((chunk ^ row) & 7);
    return row * 256 + phys * 16 + (k & 7) * 2;
}

// ---------------- smem layout (bytes) ----------------
#define SM_BIAS   0            // 8192
#define SM_XHI    8192         // 32768
#define SM_XLO    40960        // 32768
#define SM_W      73728        // 2 bufs x 49152
#define SM_TOTAL  172032

// ---------------- PTX helpers ----------------
__device__ __forceinline__ uint32_t smem_u32(const void* p) {
    uint32_t a;
    asm("{ .reg .u64 t; cvta.to.shared.u64 t, %1; cvt.u32.u64 %0, t; }" : "=r"(a) : "l"(p));
    return a;
}
__device__ __forceinline__ void cp16(uint32_t dst, const void* src) {
    asm volatile("cp.async.cg.shared.global [%0], [%1], 16;"
                 :: "r"(dst), "l"(__cvta_generic_to_global(src)) : "memory");
}
#define CP_COMMIT() asm volatile("cp.async.commit_group;" ::: "memory")
#define CP_WAIT0()  asm volatile("cp.async.wait_group 0;" ::: "memory")

__device__ __forceinline__ void ldsm_x4(uint32_t* r, uint32_t addr) {
    asm volatile("ldmatrix.sync.aligned.m8n8.x4.shared.b16 {%0,%1,%2,%3}, [%4];"
                 : "=r"(r[0]), "=r"(r[1]), "=r"(r[2]), "=r"(r[3]) : "r"(addr));
}
__device__ __forceinline__ void ldsm_x2(uint32_t* r, uint32_t addr) {
    asm volatile("ldmatrix.sync.aligned.m8n8.x2.shared.b16 {%0,%1}, [%2];"
                 : "=r"(r[0]), "=r"(r[1]) : "r"(addr));
}
__device__ __forceinline__ void mma16816(float* c, const uint32_t* a, const uint32_t* b) {
    asm volatile(
        "mma.sync.aligned.m16n8k16.row.col.f32.bf16.bf16.f32 "
        "{%0,%1,%2,%3}, {%4,%5,%6,%7}, {%8,%9}, {%0,%1,%2,%3};"
        : "+f"(c[0]), "+f"(c[1]), "+f"(c[2]), "+f"(c[3])
        : "r"(a[0]), "r"(a[1]), "r"(a[2]), "r"(a[3]), "r"(b[0]), "r"(b[1]));
}
__device__ __forceinline__ float tanh_ap(float x) {
    float y; asm("tanh.approx.f32 %0, %1;" : "=f"(y) : "f"(x)); return y;
}
__device__ __forceinline__ float sig_ap(float x) {
    return fmaf(0.5f, tanh_ap(0.5f * x), 0.5f);
}

// ---------------- prep: Wc = w_ih @ w_emb, hi/lo pack + biases ----------------
__global__ void prep_w(const float* __restrict__ w_emb, const float* __restrict__ b_emb,
                       const float* __restrict__ w_ih, const float* __restrict__ b_ih,
                       const float* __restrict__ b_hh) {
    const int g = blockIdx.x;     // 0..1535 (gate*512 + hd)
    const int i = threadIdx.x;    // 0..127  (K index)
    const float* wg = w_ih + (size_t)g * 512;
    float acc = 0.f, accb = 0.f;
#pragma unroll 8
    for (int h = 0; h < 512; h++) {
        const float w = __ldg(wg + h);
        acc  = fmaf(w, __ldg(w_emb + h * 128 + i), acc);
        accb = fmaf(w, __ldg(b_emb + h), accb);
    }
    const __nv_bfloat16 hi = __float2bfloat16(acc);
    const __nv_bfloat16 lo = __float2bfloat16(acc - __bfloat162float(hi));
    const int gate = g >> 9, hd = g & 511;
    const int ht = hd >> 5, hd_t = hd & 31;
    const int n = (hd_t >> 3) * 24 + gate * 8 + (hd_t & 7);   // row in 96-row tile
    const int off = sw_off(n, i);
    *(__nv_bfloat16*)((char*)g_W[ht][0] + off) = hi;
    *(__nv_bfloat16*)((char*)g_W[ht][1] + off) = lo;
    if (i == 0) {
        const float bc = accb + __ldg(b_ih + g);
        if (gate == 0)      g_bias[hd]       = bc + __ldg(b_hh + hd);
        else if (gate == 1) g_bias[512 + hd] = bc + __ldg(b_hh + 512 + hd);
        else { g_bias[1024 + hd] = bc; g_bias[1536 + hd] = __ldg(b_hh + 1024 + hd); }
    }
}

// ---------------- prep: x -> hi/lo bf16, packed per m-tile ----------------
__global__ void prep_x(const float* __restrict__ x) {
    const int gi = blockIdx.x * 256 + threadIdx.x;   // 16B granule
    const int m  = gi >> 4;
    const int i0 = (gi & 15) << 3;
    const float4* p = (const float4*)(x + (size_t)m * 128 + i0);
    const float4 a = p[0], c = p[1];
    const float v[8] = {a.x, a.y, a.z, a.w, c.x, c.y, c.z, c.w};
    __align__(16) __nv_bfloat16 hi[8];
    __align__(16) __nv_bfloat16 lo[8];
#pragma unroll
    for (int j = 0; j < 8; j++) {
        hi[j] = __float2bfloat16(v[j]);
        lo[j] = __float2bfloat16(v[j] - __bfloat162float(hi[j]));
    }
    const int mt = m >> 7, r = m & 127;
    const int off = sw_off(r, i0);
    *(uint4*)((char*)g_Xhi[mt] + off) = *(const uint4*)hi;
    *(uint4*)((char*)g_Xlo[mt] + off) = *(const uint4*)lo;
}

// ---------------- main fused GEMM + GRU-gate epilogue ----------------
__global__ void __launch_bounds__(256, 1)
gru_gemm(float* __restrict__ out) {
    extern __shared__ char smem[];
    const uint32_t sb = smem_u32(smem);
    const int tid = threadIdx.x, lane = tid & 31, wid = tid >> 5;
    const int warp_m = wid >> 2;      // 0..1  (64 rows each)
    const int warp_n = wid & 3;       // 0..3  (8-hd sub-block each)
    const int mt = blockIdx.x;

    // stage bias + X(hi,lo) + W tile 0, one cp.async group
    for (int i = tid; i < 512; i += 256)  cp16(sb + SM_BIAS + i * 16, (const char*)g_bias + i * 16);
    for (int i = tid; i < 2048; i += 256) cp16(sb + SM_XHI + i * 16, (const char*)g_Xhi[mt] + i * 16);
    for (int i = tid; i < 2048; i += 256) cp16(sb + SM_XLO + i * 16, (const char*)g_Xlo[mt] + i * 16);
    for (int i = tid; i < 3072; i += 256) cp16(sb + SM_W + i * 16, (const char*)g_W[0][0] + i * 16);
    CP_COMMIT();

    // per-thread fragment address components (swizzle low bits depend only on lane)
    const int rowA = warp_m * 64 + (lane & 15);            // + mb*16
    const int rowB = warp_n * 24 + (lane & 7);             // + gate*8
    const int cA   = (lane >> 4);                          // + 2*ks
    const int cB   = (lane >> 3) & 1;                      // + 2*ks
    const int low3 = lane & 7;

    // per-thread output row pointers (constant across hd-tiles)
    float* rowp[8];
#pragma unroll
    for (int mb = 0; mb < 4; mb++)
#pragma unroll
        for (int hf = 0; hf < 2; hf++) {
            const int m = mt * 128 + warp_m * 64 + mb * 16 + (lane >> 2) + hf * 8;
            const int b = m >> 9, s = m & 511;
            rowp[mb * 2 + hf] = (s < 511) ? out + ((long)(b * 511 + s)) * 512
                                          : out + H_OFF + (long)b * 512;
        }

    for (int t = 0; t < NUM_HDT; t++) {
        CP_WAIT0();
        __syncthreads();                         // W(t) ready; t-1 reads done
        if (t + 1 < NUM_HDT) {                   // prefetch W(t+1) || compute(t)
            const uint32_t dst = sb + SM_W + ((t + 1) & 1) * 49152;
            const char* src = (const char*)g_W[t + 1][0];
            for (int i = tid; i < 3072; i += 256) cp16(dst + i * 16, src + i * 16);
            CP_COMMIT();
        }

        const uint32_t wb = sb + SM_W + (t & 1) * 49152;
        float acc[4][3][4];
#pragma unroll
        for (int mb = 0; mb < 4; mb++)
#pragma unroll
            for (int nb = 0; nb < 3; nb++)
#pragma unroll
                for (int q = 0; q < 4; q++) acc[mb][nb][q] = 0.f;

#pragma unroll
        for (int seg = 0; seg < 3; seg++) {
            const uint32_t A  = sb + (seg < 2 ? SM_XHI : SM_XLO);
            const uint32_t Bs = wb + (seg == 1 ? 24576 : 0);
#pragma unroll
            for (int ks = 0; ks < 8; ks++) {
                const int ca = 2 * ks + cA;
                const int pa = (ca & 8) | ((ca ^ low3) & 7);
                const int cb = 2 * ks + cB;
                const int pb = (cb & 8) | ((cb ^ low3) & 7);
                uint32_t a[4][4], b[3][2];
#pragma unroll
                for (int mb = 0; mb < 4; mb++)
                    ldsm_x4(a[mb], A + (rowA + mb * 16) * 256 + pa * 16);
#pragma unroll
                for (int nb = 0; nb < 3; nb++)
                    ldsm_x2(b[nb], Bs + (rowB + nb * 8) * 256 + pb * 16);
#pragma unroll
                for (int mb = 0; mb < 4; mb++)
#pragma unroll
                    for (int nb = 0; nb < 3; nb++)
                        mma16816(acc[mb][nb], a[mb], b[nb]);
            }
        }

        // ---- GRU gate epilogue: gates r,z,n are nb=0,1,2 at identical cols ----
        const int hd0 = t * 32 + warp_n * 8 + (lane & 3) * 2;
        const float* bias = (const float*)smem;
        const float br0 = bias[hd0],        br1 = bias[hd0 + 1];
        const float bz0 = bias[512 + hd0],  bz1 = bias[513 + hd0];
        const float bn0 = bias[1024 + hd0], bn1 = bias[1025 + hd0];
        const float bh0 = bias[1536 + hd0], bh1 = bias[1537 + hd0];
#pragma unroll
        for (int mb = 0; mb < 4; mb++)
#pragma unroll
            for (int hf = 0; hf < 2; hf++) {
                const int q = hf * 2;
                const float r0 = sig_ap(acc[mb][0][q]     + br0);
                const float r1 = sig_ap(acc[mb][0][q + 1] + br1);
                const float z0 = sig_ap(acc[mb][1][q]     + bz0);
                const float z1 = sig_ap(acc[mb][1][q + 1] + bz1);
                const float n0 = tanh_ap(fmaf(r0, bh0, acc[mb][2][q]     + bn0));
                const float n1 = tanh_ap(fmaf(r1, bh1, acc[mb][2][q + 1] + bn1));
                float2 o;
                o.x = (1.f - z0) * n0;
                o.y = (1.f - z1) * n1;
                *(float2*)(rowp[mb * 2 + hf] + hd0) = o;
            }
    }
}

// ---------------- entry ----------------
extern "C" void kernel_launch(void* const* d_in, const int* in_sizes, int n_in,
                              void* d_out, int out_size) {
    const float* x     = (const float*)d_in[0];
    const float* w_emb = (const float*)d_in[1];
    const float* b_emb = (const float*)d_in[2];
    const float* w_ih  = (const float*)d_in[3];
    const float* b_ih  = (const float*)d_in[4];
    const float* b_hh  = (const float*)d_in[5];
    float* out = (float*)d_out;

    static bool attr_set = false;
    if (!attr_set) {
        cudaFuncSetAttribute(gru_gemm, cudaFuncAttributeMaxDynamicSharedMemorySize, SM_TOTAL);
        attr_set = true;
    }

    prep_w<<<1536, 128>>>(w_emb, b_emb, w_ih, b_ih, b_hh);
    prep_x<<<4096, 256>>>(x);
    gru_gemm<<<NUM_MT, 256, SM_TOTAL>>>(out);
}

// round 12
// speedup vs baseline: 1.0815x; 1.0815x over previous
#include <cuda_runtime.h>
#include <cuda_bf16.h>
#include <stdint.h>
#include <stddef.h>

// Problem: B=128, S=512, I=128, Hd=512.
//   gi = x @ Wc^T + bc,  Wc = w_ih @ w_emb (1536 x 128), bc = b_ih + w_ih @ b_emb
//   r = sigmoid(gi_r + b_hr); z = sigmoid(gi_z + b_hz)
//   n = tanh(gi_n + r * b_hn); h = (1-z)*n
//   out = [ H = h[:, :511, :] | h_last = h[:, 511, :] ]
//
// GEMM M=65536, N=1536, K=128 as bf16x3 (hi*hi + hi*lo + lo*hi), fp32 acc,
// via mma.sync.m16n8k16 (base-PTX tensor path).

static constexpr int NUM_MT  = 512;   // 65536 / 128 row tiles
static constexpr int NUM_HDT = 16;    // 512 / 32 hd tiles
static constexpr long H_OFF  = 128L * 511L * 512L;

// ---------------- device scratch ----------------
__device__ __nv_bfloat16 g_Xhi[512][16384];
__device__ __nv_bfloat16 g_Xlo[512][16384];
// W per hd-tile: 2 segs (hi, lo), 96 rows x 128 k each.
// Row order within tile: n = sub*24 + gate*8 + within (sub = hd_t/8, within = hd_t%8)
__device__ __nv_bfloat16 g_W[16][2][12288];
// biases: [0..512)=bc_r+b_hr [512..1024)=bc_z+b_hz [1024..1536)=bc_n [1536..2048)=b_hn
__device__ float g_bias[2048];

// XOR swizzle: byte offset of element (row, k) inside a tile (128 k per row).
__device__ __forceinline__ int sw_off(int row, int k) {
    const int chunk = k >> 3;
    const int phys  = (chunk & 8) | ((chunk ^ row) & 7);
    return row * 256 + phys * 16 + (k & 7) * 2;
}

// ---------------- smem layout (bytes) ----------------
#define SM_BIAS   0            // 8192
#define SM_XHI    8192         // 32768
#define SM_XLO    40960        // 32768
#define SM_W      73728        // 2 bufs x 49152
#define SM_TOTAL  172032

// ---------------- PTX helpers ----------------
__device__ __forceinline__ uint32_t smem_u32(const void* p) {
    uint32_t a;
    asm("{ .reg .u64 t; cvta.to.shared.u64 t, %1; cvt.u32.u64 %0, t; }" : "=r"(a) : "l"(p));
    return a;
}
__device__ __forceinline__ void cp16(uint32_t dst, const void* src) {
    asm volatile("cp.async.cg.shared.global [%0], [%1], 16;"
                 :: "r"(dst), "l"(__cvta_generic_to_global(src)) : "memory");
}
#define CP_COMMIT() asm volatile("cp.async.commit_group;" ::: "memory")
#define CP_WAIT0()  asm volatile("cp.async.wait_group 0;" ::: "memory")

__device__ __forceinline__ void ldsm_x4(uint32_t* r, uint32_t addr) {
    asm volatile("ldmatrix.sync.aligned.m8n8.x4.shared.b16 {%0,%1,%2,%3}, [%4];"
                 : "=r"(r[0]), "=r"(r[1]), "=r"(r[2]), "=r"(r[3]) : "r"(addr));
}
__device__ __forceinline__ void ldsm_x2(uint32_t* r, uint32_t addr) {
    asm volatile("ldmatrix.sync.aligned.m8n8.x2.shared.b16 {%0,%1}, [%2];"
                 : "=r"(r[0]), "=r"(r[1]) : "r"(addr));
}
__device__ __forceinline__ void mma16816(float* c, const uint32_t* a, const uint32_t* b) {
    asm volatile(
        "mma.sync.aligned.m16n8k16.row.col.f32.bf16.bf16.f32 "
        "{%0,%1,%2,%3}, {%4,%5,%6,%7}, {%8,%9}, {%0,%1,%2,%3};"
        : "+f"(c[0]), "+f"(c[1]), "+f"(c[2]), "+f"(c[3])
        : "r"(a[0]), "r"(a[1]), "r"(a[2]), "r"(a[3]), "r"(b[0]), "r"(b[1]));
}
__device__ __forceinline__ float tanh_ap(float x) {
    float y; asm("tanh.approx.f32 %0, %1;" : "=f"(y) : "f"(x)); return y;
}
__device__ __forceinline__ float sig_ap(float x) {
    return fmaf(0.5f, tanh_ap(0.5f * x), 0.5f);
}

// ---------------- prep: Wc = w_ih @ w_emb (smem-tiled), hi/lo pack + biases ----
// 192 blocks x 128 threads; block handles 8 consecutive g-rows, thread = k-col i.
__global__ void __launch_bounds__(128) prep_w(
        const float* __restrict__ w_emb, const float* __restrict__ b_emb,
        const float* __restrict__ w_ih, const float* __restrict__ b_ih,
        const float* __restrict__ b_hh) {
    __shared__ float ws[512][8];      // w_ih tile, transposed: ws[h][r]
    __shared__ float bpart[128][8];   // bias partials
    const int g0 = blockIdx.x * 8;
    const int i  = threadIdx.x;       // 0..127

    for (int idx = i; idx < 4096; idx += 128) {
        const int r = idx >> 9, h = idx & 511;
        ws[h][r] = __ldg(w_ih + (size_t)(g0 + r) * 512 + h);
    }
    __syncthreads();

    float acc[8] = {0, 0, 0, 0, 0, 0, 0, 0};
#pragma unroll 4
    for (int h = 0; h < 512; h++) {
        const float we = __ldg(w_emb + h * 128 + i);
        const float4 a0 = *(const float4*)&ws[h][0];
        const float4 a1 = *(const float4*)&ws[h][4];
        acc[0] = fmaf(a0.x, we, acc[0]); acc[1] = fmaf(a0.y, we, acc[1]);
        acc[2] = fmaf(a0.z, we, acc[2]); acc[3] = fmaf(a0.w, we, acc[3]);
        acc[4] = fmaf(a1.x, we, acc[4]); acc[5] = fmaf(a1.y, we, acc[5]);
        acc[6] = fmaf(a1.z, we, acc[6]); acc[7] = fmaf(a1.w, we, acc[7]);
    }

    // bias partials: thread i covers h = i + 128*j
    {
        float b[8] = {0, 0, 0, 0, 0, 0, 0, 0};
#pragma unroll
        for (int j = 0; j < 4; j++) {
            const int h = i + 128 * j;
            const float be = __ldg(b_emb + h);
            const float4 a0 = *(const float4*)&ws[h][0];
            const float4 a1 = *(const float4*)&ws[h][4];
            b[0] = fmaf(a0.x, be, b[0]); b[1] = fmaf(a0.y, be, b[1]);
            b[2] = fmaf(a0.z, be, b[2]); b[3] = fmaf(a0.w, be, b[3]);
            b[4] = fmaf(a1.x, be, b[4]); b[5] = fmaf(a1.y, be, b[5]);
            b[6] = fmaf(a1.z, be, b[6]); b[7] = fmaf(a1.w, be, b[7]);
        }
#pragma unroll
        for (int r = 0; r < 8; r++) bpart[i][r] = b[r];
    }

    // pack Wc hi/lo into g_W
#pragma unroll
    for (int r = 0; r < 8; r++) {
        const int g = g0 + r;
        const __nv_bfloat16 hi = __float2bfloat16(acc[r]);
        const __nv_bfloat16 lo = __float2bfloat16(acc[r] - __bfloat162float(hi));
        const int gate = g >> 9, hd = g & 511;
        const int ht = hd >> 5, hd_t = hd & 31;
        const int n = (hd_t >> 3) * 24 + gate * 8 + (hd_t & 7);
        const int off = sw_off(n, i);
        *(__nv_bfloat16*)((char*)g_W[ht][0] + off) = hi;
        *(__nv_bfloat16*)((char*)g_W[ht][1] + off) = lo;
    }

    __syncthreads();
    if (i < 8) {   // deterministic sequential reduce for bias row i
        float s = 0.f;
#pragma unroll 8
        for (int t = 0; t < 128; t++) s += bpart[t][i];
        const int g = g0 + i;
        const int gate = g >> 9, hd = g & 511;
        const float bc = s + __ldg(b_ih + g);
        if (gate == 0)      g_bias[hd]       = bc + __ldg(b_hh + hd);
        else if (gate == 1) g_bias[512 + hd] = bc + __ldg(b_hh + 512 + hd);
        else { g_bias[1024 + hd] = bc; g_bias[1536 + hd] = __ldg(b_hh + 1024 + hd); }
    }
}

// ---------------- prep: x -> hi/lo bf16, packed per m-tile ----------------
__global__ void prep_x(const float* __restrict__ x) {
    const int gi = blockIdx.x * 256 + threadIdx.x;   // 16B granule
    const int m  = gi >> 4;
    const int i0 = (gi & 15) << 3;
    const float4* p = (const float4*)(x + (size_t)m * 128 + i0);
    const float4 a = p[0], c = p[1];
    const float v[8] = {a.x, a.y, a.z, a.w, c.x, c.y, c.z, c.w};
    __align__(16) __nv_bfloat16 hi[8];
    __align__(16) __nv_bfloat16 lo[8];
#pragma unroll
    for (int j = 0; j < 8; j++) {
        hi[j] = __float2bfloat16(v[j]);
        lo[j] = __float2bfloat16(v[j] - __bfloat162float(hi[j]));
    }
    const int mt = m >> 7, r = m & 127;
    const int off = sw_off(r, i0);
    *(uint4*)((char*)g_Xhi[mt] + off) = *(const uint4*)hi;
    *(uint4*)((char*)g_Xlo[mt] + off) = *(const uint4*)lo;
}

// ---------------- main fused GEMM + GRU-gate epilogue ----------------
__global__ void __launch_bounds__(256, 1)
gru_gemm(float* __restrict__ out) {
    extern __shared__ char smem[];
    const uint32_t sb = smem_u32(smem);
    const int tid = threadIdx.x, lane = tid & 31, wid = tid >> 5;
    const int warp_m = wid >> 2;      // 0..1  (64 rows each)
    const int warp_n = wid & 3;       // 0..3  (8-hd sub-block each)
    const int mt = blockIdx.x;

    // stage bias + X(hi,lo) + W tile 0, one cp.async group
    for (int i = tid; i < 512; i += 256)  cp16(sb + SM_BIAS + i * 16, (const char*)g_bias + i * 16);
    for (int i = tid; i < 2048; i += 256) cp16(sb + SM_XHI + i * 16, (const char*)g_Xhi[mt] + i * 16);
    for (int i = tid; i < 2048; i += 256) cp16(sb + SM_XLO + i * 16, (const char*)g_Xlo[mt] + i * 16);
    for (int i = tid; i < 3072; i += 256) cp16(sb + SM_W + i * 16, (const char*)g_W[0][0] + i * 16);
    CP_COMMIT();

    // fragment address components (swizzle low bits depend only on lane)
    const int rowA = warp_m * 64 + (lane & 15);
    const int rowB = warp_n * 24 + (lane & 7);
    const int cA   = (lane >> 4);
    const int cB   = (lane >> 3) & 1;
    const int low3 = lane & 7;

    // per-thread output row pointers (constant across hd-tiles)
    float* rowp[8];
#pragma unroll
    for (int mb = 0; mb < 4; mb++)
#pragma unroll
        for (int hf = 0; hf < 2; hf++) {
            const int m = mt * 128 + warp_m * 64 + mb * 16 + (lane >> 2) + hf * 8;
            const int b = m >> 9, s = m & 511;
            rowp[mb * 2 + hf] = (s < 511) ? out + ((long)(b * 511 + s)) * 512
                                          : out + H_OFF + (long)b * 512;
        }

    for (int t = 0; t < NUM_HDT; t++) {
        CP_WAIT0();
        __syncthreads();                         // W(t) ready; t-1 reads done
        if (t + 1 < NUM_HDT) {                   // prefetch W(t+1) || compute(t)
            const uint32_t dst = sb + SM_W + ((t + 1) & 1) * 49152;
            const char* src = (const char*)g_W[t + 1][0];
            for (int i = tid; i < 3072; i += 256) cp16(dst + i * 16, src + i * 16);
            CP_COMMIT();
        }

        const uint32_t wb = sb + SM_W + (t & 1) * 49152;
        float acc[4][3][4];
#pragma unroll
        for (int mb = 0; mb < 4; mb++)
#pragma unroll
            for (int nb = 0; nb < 3; nb++)
#pragma unroll
                for (int q = 0; q < 4; q++) acc[mb][nb][q] = 0.f;

        // fragment-sharing k-loop: load a_hi, a_lo, b_hi, b_lo once per ks and
        // issue all three products (hi*hi + hi*lo + lo*hi) from them.
#pragma unroll
        for (int ks = 0; ks < 8; ks++) {
            const int ca = 2 * ks + cA;
            const int pa = (ca & 8) | ((ca ^ low3) & 7);
            const int cb = 2 * ks + cB;
            const int pb = (cb & 8) | ((cb ^ low3) & 7);
            uint32_t ah[4][4], al[4][4], bh[3][2], bl[3][2];
#pragma unroll
            for (int mb = 0; mb < 4; mb++) {
                ldsm_x4(ah[mb], sb + SM_XHI + (rowA + mb * 16) * 256 + pa * 16);
                ldsm_x4(al[mb], sb + SM_XLO + (rowA + mb * 16) * 256 + pa * 16);
            }
#pragma unroll
            for (int nb = 0; nb < 3; nb++) {
                ldsm_x2(bh[nb], wb + (rowB + nb * 8) * 256 + pb * 16);
                ldsm_x2(bl[nb], wb + 24576 + (rowB + nb * 8) * 256 + pb * 16);
            }
#pragma unroll
            for (int mb = 0; mb < 4; mb++)
#pragma unroll
                for (int nb = 0; nb < 3; nb++) {
                    mma16816(acc[mb][nb], ah[mb], bh[nb]);
                    mma16816(acc[mb][nb], ah[mb], bl[nb]);
                    mma16816(acc[mb][nb], al[mb], bh[nb]);
                }
        }

        // ---- GRU gate epilogue ----
        const int hd0 = t * 32 + warp_n * 8 + (lane & 3) * 2;
        const float* bias = (const float*)smem;
        const float br0 = bias[hd0],        br1 = bias[hd0 + 1];
        const float bz0 = bias[512 + hd0],  bz1 = bias[513 + hd0];
        const float bn0 = bias[1024 + hd0], bn1 = bias[1025 + hd0];
        const float bh0 = bias[1536 + hd0], bh1 = bias[1537 + hd0];
#pragma unroll
        for (int mb = 0; mb < 4; mb++)
#pragma unroll
            for (int hf = 0; hf < 2; hf++) {
                const int q = hf * 2;
                const float r0 = sig_ap(acc[mb][0][q]     + br0);
                const float r1 = sig_ap(acc[mb][0][q + 1] + br1);
                const float z0 = sig_ap(acc[mb][1][q]     + bz0);
                const float z1 = sig_ap(acc[mb][1][q + 1] + bz1);
                const float n0 = tanh_ap(fmaf(r0, bh0, acc[mb][2][q]     + bn0));
                const float n1 = tanh_ap(fmaf(r1, bh1, acc[mb][2][q + 1] + bn1));
                float2 o;
                o.x = (1.f - z0) * n0;
                o.y = (1.f - z1) * n1;
                *(float2*)(rowp[mb * 2 + hf] + hd0) = o;
            }
    }
}

// ---------------- entry ----------------
extern "C" void kernel_launch(void* const* d_in, const int* in_sizes, int n_in,
                              void* d_out, int out_size) {
    const float* x     = (const float*)d_in[0];
    const float* w_emb = (const float*)d_in[1];
    const float* b_emb = (const float*)d_in[2];
    const float* w_ih  = (const float*)d_in[3];
    const float* b_ih  = (const float*)d_in[4];
    const float* b_hh  = (const float*)d_in[5];
    float* out = (float*)d_out;

    static bool attr_set = false;
    if (!attr_set) {
        cudaFuncSetAttribute(gru_gemm, cudaFuncAttributeMaxDynamicSharedMemorySize, SM_TOTAL);
        attr_set = true;
    }

    prep_w<<<192, 128>>>(w_emb, b_emb, w_ih, b_ih, b_hh);
    prep_x<<<4096, 256>>>(x);
    gru_gemm<<<NUM_MT, 256, SM_TOTAL>>>(out);
}

// round 14
// speedup vs baseline: 1.1895x; 1.0998x over previous
#include <cuda_runtime.h>
#include <cuda_bf16.h>
#include <stdint.h>
#include <stddef.h>

// Problem: B=128, S=512, I=128, Hd=512.
//   gi = x @ Wc^T + bc,  Wc = w_ih @ w_emb (1536 x 128), bc = b_ih + w_ih @ b_emb
//   r = sigmoid(gi_r + b_hr); z = sigmoid(gi_z + b_hz)
//   n = tanh(gi_n + r * b_hn); h = (1-z)*n
//   out = [ H = h[:, :511, :] | h_last = h[:, 511, :] ]
//
// GEMM M=65536, N=1536, K=128 as bf16x3 (hi*hi + hi*lo + lo*hi), fp32 acc,
// via mma.sync.m16n8k16. W tiles stream via cp.async.bulk (UBLKCP) + mbarrier:
// R11 was LDGSTS-issue bound (3072 x 16B cp.async per tile = 6144 cyc/SMSP).

static constexpr int NUM_MT  = 512;   // 65536 / 128 row tiles
static constexpr int NUM_HDT = 16;    // 512 / 32 hd tiles
static constexpr long H_OFF  = 128L * 511L * 512L;

// ---------------- device scratch (16B+ aligned for cp.async.bulk) ----------------
alignas(128) __device__ __nv_bfloat16 g_Xhi[512][16384];
alignas(128) __device__ __nv_bfloat16 g_Xlo[512][16384];
// W per hd-tile: 2 segs (hi, lo), 96 rows x 128 k each.
// Row order within tile: n = sub*24 + gate*8 + within (sub = hd_t/8, within = hd_t%8)
alignas(128) __device__ __nv_bfloat16 g_W[16][2][12288];
// biases: [0..512)=bc_r+b_hr [512..1024)=bc_z+b_hz [1024..1536)=bc_n [1536..2048)=b_hn
alignas(128) __device__ float g_bias[2048];

// XOR swizzle: byte offset of element (row, k) inside a tile (128 k per row).
__device__ __forceinline__ int sw_off(int row, int k) {
    const int chunk = k >> 3;
    const int phys  = (chunk & 8) | ((chunk ^ row) & 7);
    return row * 256 + phys * 16 + (k & 7) * 2;
}

// ---------------- smem layout (bytes) ----------------
#define SM_MBAR   0            // 3 x 8B mbarriers
#define SM_BIAS   1024         // 8192
#define SM_XHI    10240        // 32768
#define SM_XLO    43008        // 32768
#define SM_W      75776        // 3 bufs x 49152
#define SM_TOTAL  223232       // fits 227KB opt-in

// ---------------- PTX helpers ----------------
__device__ __forceinline__ uint32_t smem_u32(const void* p) {
    uint32_t a;
    asm("{ .reg .u64 t; cvta.to.shared.u64 t, %1; cvt.u32.u64 %0, t; }" : "=r"(a) : "l"(p));
    return a;
}
__device__ __forceinline__ void bulk_g2s(uint32_t dst, const void* src, uint32_t bytes,
                                         uint32_t mbar) {
    asm volatile(
        "cp.async.bulk.shared::cluster.global.mbarrier::complete_tx::bytes [%0], [%1], %2, [%3];"
        :: "r"(dst), "l"(__cvta_generic_to_global(src)), "r"(bytes), "r"(mbar) : "memory");
}
#define MBAR_INIT(mb, c)  asm volatile("mbarrier.init.shared.b64 [%0], %1;" :: "r"(mb), "r"(c) : "memory")
#define EXPECT_TX(mb, n)  asm volatile("mbarrier.arrive.expect_tx.shared.b64 _, [%0], %1;" :: "r"(mb), "r"(n) : "memory")

__device__ __forceinline__ void mbar_wait(uint32_t mb, uint32_t parity) {
    asm volatile(
        "{ .reg .pred P;\n\t"
        "WL%=: mbarrier.try_wait.parity.acquire.cta.shared::cta.b64 P, [%0], %1, 0x989680;\n\t"
        "@P bra WD%=;\n\t"
        "bra WL%=;\n\t"
        "WD%=: }"
        :: "r"(mb), "r"(parity) : "memory");
}

__device__ __forceinline__ void ldsm_x4(uint32_t* r, uint32_t addr) {
    asm volatile("ldmatrix.sync.aligned.m8n8.x4.shared.b16 {%0,%1,%2,%3}, [%4];"
                 : "=r"(r[0]), "=r"(r[1]), "=r"(r[2]), "=r"(r[3]) : "r"(addr));
}
__device__ __forceinline__ void ldsm_x2(uint32_t* r, uint32_t addr) {
    asm volatile("ldmatrix.sync.aligned.m8n8.x2.shared.b16 {%0,%1}, [%2];"
                 : "=r"(r[0]), "=r"(r[1]) : "r"(addr));
}
__device__ __forceinline__ void mma16816(float* c, const uint32_t* a, const uint32_t* b) {
    asm volatile(
        "mma.sync.aligned.m16n8k16.row.col.f32.bf16.bf16.f32 "
        "{%0,%1,%2,%3}, {%4,%5,%6,%7}, {%8,%9}, {%0,%1,%2,%3};"
        : "+f"(c[0]), "+f"(c[1]), "+f"(c[2]), "+f"(c[3])
        : "r"(a[0]), "r"(a[1]), "r"(a[2]), "r"(a[3]), "r"(b[0]), "r"(b[1]));
}
__device__ __forceinline__ float tanh_ap(float x) {
    float y; asm("tanh.approx.f32 %0, %1;" : "=f"(y) : "f"(x)); return y;
}
__device__ __forceinline__ float sig_ap(float x) {
    return fmaf(0.5f, tanh_ap(0.5f * x), 0.5f);
}

// ---------------- fused prep: blocks [0,4096) = x pack, [4096,4288) = Wc ------
__global__ void __launch_bounds__(256) prep_all(
        const float* __restrict__ x, const float* __restrict__ w_emb,
        const float* __restrict__ b_emb, const float* __restrict__ w_ih,
        const float* __restrict__ b_ih, const float* __restrict__ b_hh) {
    __shared__ float ws[512][8];      // w_ih tile transposed: ws[h][r]
    __shared__ float part[2][8][128]; // split-h partials
    __shared__ float bpart[128][8];   // bias partials

    if (blockIdx.x < 4096) {          // ---- x -> hi/lo bf16, packed per m-tile ----
        const int gi = blockIdx.x * 256 + threadIdx.x;   // 16B granule
        const int m  = gi >> 4;
        const int i0 = (gi & 15) << 3;
        const float4* p = (const float4*)(x + (size_t)m * 128 + i0);
        const float4 a = p[0], c = p[1];
        const float v[8] = {a.x, a.y, a.z, a.w, c.x, c.y, c.z, c.w};
        __align__(16) __nv_bfloat16 hi[8];
        __align__(16) __nv_bfloat16 lo[8];
#pragma unroll
        for (int j = 0; j < 8; j++) {
            hi[j] = __float2bfloat16(v[j]);
            lo[j] = __float2bfloat16(v[j] - __bfloat162float(hi[j]));
        }
        const int mt = m >> 7, r = m & 127;
        const int off = sw_off(r, i0);
        *(uint4*)((char*)g_Xhi[mt] + off) = *(const uint4*)hi;
        *(uint4*)((char*)g_Xlo[mt] + off) = *(const uint4*)lo;
        return;
    }

    // ---- Wc = w_ih @ w_emb (8 g-rows per block, h split across 2 groups) ----
    const int g0 = (blockIdx.x - 4096) * 8;
    const int tid = threadIdx.x;
    const int hc = tid >> 7;          // 0..1: h-chunk
    const int i  = tid & 127;         // k column

    for (int idx = tid; idx < 4096; idx += 256) {
        const int r = idx >> 9, h = idx & 511;
        ws[h][r] = __ldg(w_ih + (size_t)(g0 + r) * 512 + h);
    }
    __syncthreads();

    float acc[8] = {0, 0, 0, 0, 0, 0, 0, 0};
    const int h0 = hc << 8;
#pragma unroll 4
    for (int hh = 0; hh < 256; hh++) {
        const int h = h0 + hh;
        const float we = __ldg(w_emb + h * 128 + i);
        const float4 a0 = *(const float4*)&ws[h][0];
        const float4 a1 = *(const float4*)&ws[h][4];
        acc[0] = fmaf(a0.x, we, acc[0]); acc[1] = fmaf(a0.y, we, acc[1]);
        acc[2] = fmaf(a0.z, we, acc[2]); acc[3] = fmaf(a0.w, we, acc[3]);
        acc[4] = fmaf(a1.x, we, acc[4]); acc[5] = fmaf(a1.y, we, acc[5]);
        acc[6] = fmaf(a1.z, we, acc[6]); acc[7] = fmaf(a1.w, we, acc[7]);
    }
#pragma unroll
    for (int r = 0; r < 8; r++) part[hc][r][i] = acc[r];

    if (hc == 0) {                    // bias partials
        float b[8] = {0, 0, 0, 0, 0, 0, 0, 0};
#pragma unroll
        for (int j = 0; j < 4; j++) {
            const int h = i + 128 * j;
            const float be = __ldg(b_emb + h);
            const float4 a0 = *(const float4*)&ws[h][0];
            const float4 a1 = *(const float4*)&ws[h][4];
            b[0] = fmaf(a0.x, be, b[0]); b[1] = fmaf(a0.y, be, b[1]);
            b[2] = fmaf(a0.z, be, b[2]); b[3] = fmaf(a0.w, be, b[3]);
            b[4] = fmaf(a1.x, be, b[4]); b[5] = fmaf(a1.y, be, b[5]);
            b[6] = fmaf(a1.z, be, b[6]); b[7] = fmaf(a1.w, be, b[7]);
        }
#pragma unroll
        for (int r = 0; r < 8; r++) bpart[i][r] = b[r];
    }
    __syncthreads();

    if (hc == 0) {                    // combine, pack hi/lo
#pragma unroll
        for (int r = 0; r < 8; r++) {
            const float v = part[0][r][i] + part[1][r][i];
            const __nv_bfloat16 hi = __float2bfloat16(v);
            const __nv_bfloat16 lo = __float2bfloat16(v - __bfloat162float(hi));
            const int g = g0 + r;
            const int gate = g >> 9, hd = g & 511;
            const int ht = hd >> 5, hd_t = hd & 31;
            const int n = (hd_t >> 3) * 24 + gate * 8 + (hd_t & 7);
            const int off = sw_off(n, i);
            *(__nv_bfloat16*)((char*)g_W[ht][0] + off) = hi;
            *(__nv_bfloat16*)((char*)g_W[ht][1] + off) = lo;
        }
        if (i < 8) {                  // deterministic bias reduce for row i
            float s = 0.f;
#pragma unroll 8
            for (int t = 0; t < 128; t++) s += bpart[t][i];
            const int g = g0 + i;
            const int gate = g >> 9, hd = g & 511;
            const float bc = s + __ldg(b_ih + g);
            if (gate == 0)      g_bias[hd]       = bc + __ldg(b_hh + hd);
            else if (gate == 1) g_bias[512 + hd] = bc + __ldg(b_hh + 512 + hd);
            else { g_bias[1024 + hd] = bc; g_bias[1536 + hd] = __ldg(b_hh + 1024 + hd); }
        }
    }
}

// ---------------- main fused GEMM + GRU-gate epilogue ----------------
__global__ void __launch_bounds__(256, 1)
gru_gemm(float* __restrict__ out) {
    extern __shared__ char smem[];
    const uint32_t sb = smem_u32(smem);
    const int tid = threadIdx.x, lane = tid & 31, wid = tid >> 5;
    const int warp_m = wid >> 2;      // 0..1  (64 rows each)
    const int warp_n = wid & 3;       // 0..3  (8-hd sub-block each)
    const int mt = blockIdx.x;

    if (tid == 0) {
        MBAR_INIT(sb + SM_MBAR,      1);
        MBAR_INIT(sb + SM_MBAR + 8,  1);
        MBAR_INIT(sb + SM_MBAR + 16, 1);
    }
    __syncthreads();
    if (tid == 0) {                   // prologue: bias + X + W0..W2, bulk copies
        EXPECT_TX(sb + SM_MBAR, 8192u + 32768u + 32768u + 49152u);
        bulk_g2s(sb + SM_BIAS, g_bias,    8192,  sb + SM_MBAR);
        bulk_g2s(sb + SM_XHI,  g_Xhi[mt], 32768, sb + SM_MBAR);
        bulk_g2s(sb + SM_XLO,  g_Xlo[mt], 32768, sb + SM_MBAR);
        bulk_g2s(sb + SM_W,    g_W[0][0], 49152, sb + SM_MBAR);
        EXPECT_TX(sb + SM_MBAR + 8, 49152u);
        bulk_g2s(sb + SM_W + 49152, g_W[1][0], 49152, sb + SM_MBAR + 8);
        EXPECT_TX(sb + SM_MBAR + 16, 49152u);
        bulk_g2s(sb + SM_W + 98304, g_W[2][0], 49152, sb + SM_MBAR + 16);
    }

    // fragment address components (swizzle low bits depend only on lane)
    const int rowA = warp_m * 64 + (lane & 15);
    const int rowB = warp_n * 24 + (lane & 7);
    const int cA   = (lane >> 4);
    const int cB   = (lane >> 3) & 1;
    const int low3 = lane & 7;

    // per-thread output row pointers (constant across hd-tiles)
    float* rowp[8];
#pragma unroll
    for (int mb = 0; mb < 4; mb++)
#pragma unroll
        for (int hf = 0; hf < 2; hf++) {
            const int m = mt * 128 + warp_m * 64 + mb * 16 + (lane >> 2) + hf * 8;
            const int b = m >> 9, s = m & 511;
            rowp[mb * 2 + hf] = (s < 511) ? out + ((long)(b * 511 + s)) * 512
                                          : out + H_OFF + (long)b * 512;
        }

    int buf = 0, ph = 0;
    for (int t = 0; t < NUM_HDT; t++) {
        mbar_wait(sb + SM_MBAR + 8 * buf, ph);   // W(t) (+ X/bias at t=0) ready

        const uint32_t wb = sb + SM_W + buf * 49152;
        float acc[4][3][4];
#pragma unroll
        for (int mb = 0; mb < 4; mb++)
#pragma unroll
            for (int nb = 0; nb < 3; nb++)
#pragma unroll
                for (int q = 0; q < 4; q++) acc[mb][nb][q] = 0.f;

        // fragment-sharing k-loop: a_hi, a_lo, b_hi, b_lo loaded once per ks,
        // three products (hi*hi + hi*lo + lo*hi) issued from them.
#pragma unroll
        for (int ks = 0; ks < 8; ks++) {
            const int ca = 2 * ks + cA;
            const int pa = (ca & 8) | ((ca ^ low3) & 7);
            const int cb = 2 * ks + cB;
            const int pb = (cb & 8) | ((cb ^ low3) & 7);
            uint32_t ah[4][4], al[4][4], bh[3][2], bl[3][2];
#pragma unroll
            for (int mb = 0; mb < 4; mb++) {
                ldsm_x4(ah[mb], sb + SM_XHI + (rowA + mb * 16) * 256 + pa * 16);
                ldsm_x4(al[mb], sb + SM_XLO + (rowA + mb * 16) * 256 + pa * 16);
            }
#pragma unroll
            for (int nb = 0; nb < 3; nb++) {
                ldsm_x2(bh[nb], wb + (rowB + nb * 8) * 256 + pb * 16);
                ldsm_x2(bl[nb], wb + 24576 + (rowB + nb * 8) * 256 + pb * 16);
            }
#pragma unroll
            for (int mb = 0; mb < 4; mb++)
#pragma unroll
                for (int nb = 0; nb < 3; nb++) {
                    mma16816(acc[mb][nb], ah[mb], bh[nb]);
                    mma16816(acc[mb][nb], ah[mb], bl[nb]);
                    mma16816(acc[mb][nb], al[mb], bh[nb]);
                }
        }

        // ---- GRU gate epilogue ----
        const int hd0 = t * 32 + warp_n * 8 + (lane & 3) * 2;
        const float* bias = (const float*)(smem + SM_BIAS);
        const float br0 = bias[hd0],        br1 = bias[hd0 + 1];
        const float bz0 = bias[512 + hd0],  bz1 = bias[513 + hd0];
        const float bn0 = bias[1024 + hd0], bn1 = bias[1025 + hd0];
        const float bh0 = bias[1536 + hd0], bh1 = bias[1537 + hd0];
#pragma unroll
        for (int mb = 0; mb < 4; mb++)
#pragma unroll
            for (int hf = 0; hf < 2; hf++) {
                const int q = hf * 2;
                const float r0 = sig_ap(acc[mb][0][q]     + br0);
                const float r1 = sig_ap(acc[mb][0][q + 1] + br1);
                const float z0 = sig_ap(acc[mb][1][q]     + bz0);
                const float z1 = sig_ap(acc[mb][1][q + 1] + bz1);
                const float n0 = tanh_ap(fmaf(r0, bh0, acc[mb][2][q]     + bn0));
                const float n1 = tanh_ap(fmaf(r1, bh1, acc[mb][2][q + 1] + bn1));
                float2 o;
                o.x = (1.f - z0) * n0;
                o.y = (1.f - z1) * n1;
                *(float2*)(rowp[mb * 2 + hf] + hd0) = o;
            }

        __syncthreads();                          // all reads of buffer done
        if (t + 3 < NUM_HDT && tid == 0) {        // refill this buffer with W(t+3)
            EXPECT_TX(sb + SM_MBAR + 8 * buf, 49152u);
            bulk_g2s(wb, g_W[t + 3][0], 49152, sb + SM_MBAR + 8 * buf);
        }
        if (++buf == 3) { buf = 0; ph ^= 1; }
    }
}

// ---------------- entry ----------------
extern "C" void kernel_launch(void* const* d_in, const int* in_sizes, int n_in,
                              void* d_out, int out_size) {
    const float* x     = (const float*)d_in[0];
    const float* w_emb = (const float*)d_in[1];
    const float* b_emb = (const float*)d_in[2];
    const float* w_ih  = (const float*)d_in[3];
    const float* b_ih  = (const float*)d_in[4];
    const float* b_hh  = (const float*)d_in[5];
    float* out = (float*)d_out;

    static bool attr_set = false;
    if (!attr_set) {
        cudaFuncSetAttribute(gru_gemm, cudaFuncAttributeMaxDynamicSharedMemorySize, SM_TOTAL);
        attr_set = true;
    }

    prep_all<<<4288, 256>>>(x, w_emb, b_emb, w_ih, b_ih, b_hh);
    gru_gemm<<<NUM_MT, 256, SM_TOTAL>>>(out);
}

// round 16
// speedup vs baseline: 1.3285x; 1.1169x over previous
#include <cuda_runtime.h>
#include <cuda_bf16.h>
#include <stdint.h>
#include <stddef.h>

// Problem: B=128, S=512, I=128, Hd=512.
//   gi = x @ Wc^T + bc,  Wc = w_ih @ w_emb (1536 x 128), bc = b_ih + w_ih @ b_emb
//   r = sigmoid(gi_r + b_hr); z = sigmoid(gi_z + b_hz)
//   n = tanh(gi_n + r * b_hn); h = (1-z)*n
//   out = [ H = h[:, :511, :] | h_last = h[:, 511, :] ]
//
// GEMM M=65536, N=1536, K=128 as bf16x3 (hi*hi + hi*lo + lo*hi), fp32 acc,
// via mma.sync.m16n8k16. W streams via cp.async.bulk + mbarrier ring.
// R14: 512-thread CTAs (occupancy/overlap) + 1024-way work grain (wave balance).

static constexpr int NUM_MT  = 512;   // 65536 / 128 row tiles
static constexpr long H_OFF  = 128L * 511L * 512L;

// ---------------- device scratch ----------------
alignas(128) __device__ __nv_bfloat16 g_Xhi[512][16384];
alignas(128) __device__ __nv_bfloat16 g_Xlo[512][16384];
// W per hd-tile: 2 segs (hi, lo), 96 rows x 128 k each.
// Row order within tile: n = sub*24 + gate*8 + within (sub = hd_t/8, within = hd_t%8)
alignas(128) __device__ __nv_bfloat16 g_W[16][2][12288];
// biases: [0..512)=bc_r+b_hr [512..1024)=bc_z+b_hz [1024..1536)=bc_n [1536..2048)=b_hn
alignas(128) __device__ float g_bias[2048];

// XOR swizzle: byte offset of element (row, k) inside a tile (128 k per row).
__device__ __forceinline__ int sw_off(int row, int k) {
    const int chunk = k >> 3;
    const int phys  = (chunk & 8) | ((chunk ^ row) & 7);
    return row * 256 + phys * 16 + (k & 7) * 2;
}

// ---------------- smem layout (bytes) ----------------
#define SM_MBAR   0            // 3 x 8B mbarriers
#define SM_BIAS   1024         // 8192
#define SM_XHI    10240        // 32768
#define SM_XLO    43008        // 32768
#define SM_W      75776        // 3 bufs x 49152
#define SM_TOTAL  223232

// ---------------- PTX helpers ----------------
__device__ __forceinline__ uint32_t smem_u32(const void* p) {
    uint32_t a;
    asm("{ .reg .u64 t; cvta.to.shared.u64 t, %1; cvt.u32.u64 %0, t; }" : "=r"(a) : "l"(p));
    return a;
}
__device__ __forceinline__ void bulk_g2s(uint32_t dst, const void* src, uint32_t bytes,
                                         uint32_t mbar) {
    asm volatile(
        "cp.async.bulk.shared::cluster.global.mbarrier::complete_tx::bytes [%0], [%1], %2, [%3];"
        :: "r"(dst), "l"(__cvta_generic_to_global(src)), "r"(bytes), "r"(mbar) : "memory");
}
#define MBAR_INIT(mb, c)  asm volatile("mbarrier.init.shared.b64 [%0], %1;" :: "r"(mb), "r"(c) : "memory")
#define EXPECT_TX(mb, n)  asm volatile("mbarrier.arrive.expect_tx.shared.b64 _, [%0], %1;" :: "r"(mb), "r"(n) : "memory")

__device__ __forceinline__ void mbar_wait(uint32_t mb, uint32_t parity) {
    asm volatile(
        "{ .reg .pred P;\n\t"
        "WL%=: mbarrier.try_wait.parity.acquire.cta.shared::cta.b64 P, [%0], %1, 0x989680;\n\t"
        "@P bra WD%=;\n\t"
        "bra WL%=;\n\t"
        "WD%=: }"
        :: "r"(mb), "r"(parity) : "memory");
}

__device__ __forceinline__ void ldsm_x4(uint32_t* r, uint32_t addr) {
    asm volatile("ldmatrix.sync.aligned.m8n8.x4.shared.b16 {%0,%1,%2,%3}, [%4];"
                 : "=r"(r[0]), "=r"(r[1]), "=r"(r[2]), "=r"(r[3]) : "r"(addr));
}
__device__ __forceinline__ void ldsm_x2(uint32_t* r, uint32_t addr) {
    asm volatile("ldmatrix.sync.aligned.m8n8.x2.shared.b16 {%0,%1}, [%2];"
                 : "=r"(r[0]), "=r"(r[1]) : "r"(addr));
}
__device__ __forceinline__ void mma16816(float* c, const uint32_t* a, const uint32_t* b) {
    asm volatile(
        "mma.sync.aligned.m16n8k16.row.col.f32.bf16.bf16.f32 "
        "{%0,%1,%2,%3}, {%4,%5,%6,%7}, {%8,%9}, {%0,%1,%2,%3};"
        : "+f"(c[0]), "+f"(c[1]), "+f"(c[2]), "+f"(c[3])
        : "r"(a[0]), "r"(a[1]), "r"(a[2]), "r"(a[3]), "r"(b[0]), "r"(b[1]));
}
__device__ __forceinline__ float tanh_ap(float x) {
    float y; asm("tanh.approx.f32 %0, %1;" : "=f"(y) : "f"(x)); return y;
}
__device__ __forceinline__ float sig_ap(float x) {
    return fmaf(0.5f, tanh_ap(0.5f * x), 0.5f);
}

// ---------------- fused prep: blocks [0,384) = Wc (FIRST), rest = x pack ------
__global__ void __launch_bounds__(256) prep_all(
        const float* __restrict__ x, const float* __restrict__ w_emb,
        const float* __restrict__ b_emb, const float* __restrict__ w_ih,
        const float* __restrict__ b_ih, const float* __restrict__ b_hh) {
    __shared__ float ws[512][4];      // w_ih tile transposed: ws[h][r]
    __shared__ float part[2][4][128]; // split-h partials
    __shared__ float bpart[128][4];   // bias partials

    if (blockIdx.x >= 384) {          // ---- x -> hi/lo bf16, packed per m-tile ----
        const int gi = (blockIdx.x - 384) * 256 + threadIdx.x;   // 16B granule
        const int m  = gi >> 4;
        const int i0 = (gi & 15) << 3;
        const float4* p = (const float4*)(x + (size_t)m * 128 + i0);
        const float4 a = p[0], c = p[1];
        const float v[8] = {a.x, a.y, a.z, a.w, c.x, c.y, c.z, c.w};
        __align__(16) __nv_bfloat16 hi[8];
        __align__(16) __nv_bfloat16 lo[8];
#pragma unroll
        for (int j = 0; j < 8; j++) {
            hi[j] = __float2bfloat16(v[j]);
            lo[j] = __float2bfloat16(v[j] - __bfloat162float(hi[j]));
        }
        const int mt = m >> 7, r = m & 127;
        const int off = sw_off(r, i0);
        *(uint4*)((char*)g_Xhi[mt] + off) = *(const uint4*)hi;
        *(uint4*)((char*)g_Xlo[mt] + off) = *(const uint4*)lo;
        return;
    }

    // ---- Wc = w_ih @ w_emb (4 g-rows per block, h split across 2 groups) ----
    const int g0 = blockIdx.x * 4;
    const int tid = threadIdx.x;
    const int hc = tid >> 7;          // 0..1: h-chunk
    const int i  = tid & 127;         // k column

    for (int idx = tid; idx < 2048; idx += 256) {
        const int r = idx >> 9, h = idx & 511;
        ws[h][r] = __ldg(w_ih + (size_t)(g0 + r) * 512 + h);
    }
    __syncthreads();

    float acc[4] = {0, 0, 0, 0};
    const int h0 = hc << 8;
#pragma unroll 4
    for (int hh = 0; hh < 256; hh++) {
        const int h = h0 + hh;
        const float we = __ldg(w_emb + h * 128 + i);
        const float4 a0 = *(const float4*)&ws[h][0];
        acc[0] = fmaf(a0.x, we, acc[0]); acc[1] = fmaf(a0.y, we, acc[1]);
        acc[2] = fmaf(a0.z, we, acc[2]); acc[3] = fmaf(a0.w, we, acc[3]);
    }
#pragma unroll
    for (int r = 0; r < 4; r++) part[hc][r][i] = acc[r];

    if (hc == 0) {                    // bias partials
        float b[4] = {0, 0, 0, 0};
#pragma unroll
        for (int j = 0; j < 4; j++) {
            const int h = i + 128 * j;
            const float be = __ldg(b_emb + h);
            const float4 a0 = *(const float4*)&ws[h][0];
            b[0] = fmaf(a0.x, be, b[0]); b[1] = fmaf(a0.y, be, b[1]);
            b[2] = fmaf(a0.z, be, b[2]); b[3] = fmaf(a0.w, be, b[3]);
        }
#pragma unroll
        for (int r = 0; r < 4; r++) bpart[i][r] = b[r];
    }
    __syncthreads();

    if (hc == 0) {                    // combine, pack hi/lo
#pragma unroll
        for (int r = 0; r < 4; r++) {
            const float v = part[0][r][i] + part[1][r][i];
            const __nv_bfloat16 hi = __float2bfloat16(v);
            const __nv_bfloat16 lo = __float2bfloat16(v - __bfloat162float(hi));
            const int g = g0 + r;
            const int gate = g >> 9, hd = g & 511;
            const int ht = hd >> 5, hd_t = hd & 31;
            const int n = (hd_t >> 3) * 24 + gate * 8 + (hd_t & 7);
            const int off = sw_off(n, i);
            *(__nv_bfloat16*)((char*)g_W[ht][0] + off) = hi;
            *(__nv_bfloat16*)((char*)g_W[ht][1] + off) = lo;
        }
        if (i < 4) {                  // deterministic bias reduce for row i
            float s = 0.f;
#pragma unroll 8
            for (int t = 0; t < 128; t++) s += bpart[t][i];
            const int g = g0 + i;
            const int gate = g >> 9, hd = g & 511;
            const float bc = s + __ldg(b_ih + g);
            if (gate == 0)      g_bias[hd]       = bc + __ldg(b_hh + hd);
            else if (gate == 1) g_bias[512 + hd] = bc + __ldg(b_hh + 512 + hd);
            else { g_bias[1024 + hd] = bc; g_bias[1536 + hd] = __ldg(b_hh + 1024 + hd); }
        }
    }
}

// ---------------- main fused GEMM + GRU-gate epilogue ----------------
// grid = 1024: CTA = (m-tile mt, hd-half). 512 threads: warp_m 0..3 x warp_n 0..3.
__global__ void __launch_bounds__(512, 1)
gru_gemm(float* __restrict__ out) {
    extern __shared__ char smem[];
    const uint32_t sb = smem_u32(smem);
    const int tid = threadIdx.x, lane = tid & 31, wid = tid >> 5;
    const int warp_m = wid >> 2;      // 0..3  (32 rows each)
    const int warp_n = wid & 3;       // 0..3  (8-hd sub-block each)
    const int mt   = blockIdx.x >> 1;
    const int thd0 = (blockIdx.x & 1) * 8;   // first hd-tile of this CTA's half

    if (tid == 0) {
        MBAR_INIT(sb + SM_MBAR,      1);
        MBAR_INIT(sb + SM_MBAR + 8,  1);
        MBAR_INIT(sb + SM_MBAR + 16, 1);
    }
    __syncthreads();
    if (tid == 0) {                   // prologue: bias + X + W[thd0..thd0+2]
        EXPECT_TX(sb + SM_MBAR, 8192u + 32768u + 32768u + 49152u);
        bulk_g2s(sb + SM_BIAS, g_bias,    8192,  sb + SM_MBAR);
        bulk_g2s(sb + SM_XHI,  g_Xhi[mt], 32768, sb + SM_MBAR);
        bulk_g2s(sb + SM_XLO,  g_Xlo[mt], 32768, sb + SM_MBAR);
        bulk_g2s(sb + SM_W,    g_W[thd0][0], 49152, sb + SM_MBAR);
        EXPECT_TX(sb + SM_MBAR + 8, 49152u);
        bulk_g2s(sb + SM_W + 49152, g_W[thd0 + 1][0], 49152, sb + SM_MBAR + 8);
        EXPECT_TX(sb + SM_MBAR + 16, 49152u);
        bulk_g2s(sb + SM_W + 98304, g_W[thd0 + 2][0], 49152, sb + SM_MBAR + 16);
    }

    // fragment address components (swizzle low bits depend only on lane)
    const int rowA = warp_m * 32 + (lane & 15);
    const int rowB = warp_n * 24 + (lane & 7);
    const int cA   = (lane >> 4);
    const int cB   = (lane >> 3) & 1;
    const int low3 = lane & 7;

    // per-thread output row pointers
    float* rowp[4];
#pragma unroll
    for (int mb = 0; mb < 2; mb++)
#pragma unroll
        for (int hf = 0; hf < 2; hf++) {
            const int m = mt * 128 + warp_m * 32 + mb * 16 + (lane >> 2) + hf * 8;
            const int b = m >> 9, s = m & 511;
            rowp[mb * 2 + hf] = (s < 511) ? out + ((long)(b * 511 + s)) * 512
                                          : out + H_OFF + (long)b * 512;
        }

    int buf = 0, ph = 0;
    for (int tt = 0; tt < 8; tt++) {
        const int t = thd0 + tt;
        mbar_wait(sb + SM_MBAR + 8 * buf, ph);   // W(t) (+ X/bias at tt=0) ready

        const uint32_t wb = sb + SM_W + buf * 49152;
        float acc[2][3][4];
#pragma unroll
        for (int mb = 0; mb < 2; mb++)
#pragma unroll
            for (int nb = 0; nb < 3; nb++)
#pragma unroll
                for (int q = 0; q < 4; q++) acc[mb][nb][q] = 0.f;

        // fragment-sharing k-loop: a_hi, a_lo, b_hi, b_lo loaded once per ks,
        // three products (hi*hi + hi*lo + lo*hi) issued from them.
#pragma unroll
        for (int ks = 0; ks < 8; ks++) {
            const int ca = 2 * ks + cA;
            const int pa = (ca & 8) | ((ca ^ low3) & 7);
            const int cb = 2 * ks + cB;
            const int pb = (cb & 8) | ((cb ^ low3) & 7);
            uint32_t ah[2][4], al[2][4], bh[3][2], bl[3][2];
#pragma unroll
            for (int mb = 0; mb < 2; mb++) {
                ldsm_x4(ah[mb], sb + SM_XHI + (rowA + mb * 16) * 256 + pa * 16);
                ldsm_x4(al[mb], sb + SM_XLO + (rowA + mb * 16) * 256 + pa * 16);
            }
#pragma unroll
            for (int nb = 0; nb < 3; nb++) {
                ldsm_x2(bh[nb], wb + (rowB + nb * 8) * 256 + pb * 16);
                ldsm_x2(bl[nb], wb + 24576 + (rowB + nb * 8) * 256 + pb * 16);
            }
#pragma unroll
            for (int mb = 0; mb < 2; mb++)
#pragma unroll
                for (int nb = 0; nb < 3; nb++) {
                    mma16816(acc[mb][nb], ah[mb], bh[nb]);
                    mma16816(acc[mb][nb], ah[mb], bl[nb]);
                    mma16816(acc[mb][nb], al[mb], bh[nb]);
                }
        }

        // ---- GRU gate epilogue ----
        const int hd0 = t * 32 + warp_n * 8 + (lane & 3) * 2;
        const float* bias = (const float*)(smem + SM_BIAS);
        const float br0 = bias[hd0],        br1 = bias[hd0 + 1];
        const float bz0 = bias[512 + hd0],  bz1 = bias[513 + hd0];
        const float bn0 = bias[1024 + hd0], bn1 = bias[1025 + hd0];
        const float bh0 = bias[1536 + hd0], bh1 = bias[1537 + hd0];
#pragma unroll
        for (int mb = 0; mb < 2; mb++)
#pragma unroll
            for (int hf = 0; hf < 2; hf++) {
                const int q = hf * 2;
                const float r0 = sig_ap(acc[mb][0][q]     + br0);
                const float r1 = sig_ap(acc[mb][0][q + 1] + br1);
                const float z0 = sig_ap(acc[mb][1][q]     + bz0);
                const float z1 = sig_ap(acc[mb][1][q + 1] + bz1);
                const float n0 = tanh_ap(fmaf(r0, bh0, acc[mb][2][q]     + bn0));
                const float n1 = tanh_ap(fmaf(r1, bh1, acc[mb][2][q + 1] + bn1));
                float2 o;
                o.x = (1.f - z0) * n0;
                o.y = (1.f - z1) * n1;
                *(float2*)(rowp[mb * 2 + hf] + hd0) = o;
            }

        __syncthreads();                          // all reads of buffer done
        if (tt + 3 < 8 && tid == 0) {             // refill this buffer with W(t+3)
            EXPECT_TX(sb + SM_MBAR + 8 * buf, 49152u);
            bulk_g2s(wb, g_W[t + 3][0], 49152, sb + SM_MBAR + 8 * buf);
        }
        if (++buf == 3) { buf = 0; ph ^= 1; }
    }
}

// ---------------- entry ----------------
extern "C" void kernel_launch(void* const* d_in, const int* in_sizes, int n_in,
                              void* d_out, int out_size) {
    const float* x     = (const float*)d_in[0];
    const float* w_emb = (const float*)d_in[1];
    const float* b_emb = (const float*)d_in[2];
    const float* w_ih  = (const float*)d_in[3];
    const float* b_ih  = (const float*)d_in[4];
    const float* b_hh  = (const float*)d_in[5];
    float* out = (float*)d_out;

    static bool attr_set = false;
    if (!attr_set) {
        cudaFuncSetAttribute(gru_gemm, cudaFuncAttributeMaxDynamicSharedMemorySize, SM_TOTAL);
        attr_set = true;
    }

    prep_all<<<4480, 256>>>(x, w_emb, b_emb, w_ih, b_ih, b_hh);
    gru_gemm<<<NUM_MT * 2, 512, SM_TOTAL>>>(out);
}